// round 6
// baseline (speedup 1.0000x reference)
#include <cuda_runtime.h>
#include <math.h>

// ---------------- problem constants ----------------
#define NB   800          // 8*100 images
#define IMGD 128

// ---------------- device scratch ----------------
__device__ float  g_pool1[NB*4*30*30];     // 11.5 MB
__device__ float  g_pool2[NB*8*5*5];
__device__ double g_stats1[8];             // sum[4], sumsq[4]
__device__ double g_stats2[16];            // sum[8], sumsq[8]
__device__ float  g_zR[NB*5];              // z0,z1,r00,r01,r11 per sample

// ---------------- f32x2 helpers ----------------
typedef unsigned long long ull;
__device__ __forceinline__ ull pack2(float a, float b) {
    ull r; asm("mov.b64 %0, {%1,%2};" : "=l"(r) : "f"(a), "f"(b)); return r;
}
__device__ __forceinline__ void unpack2(ull v, float& a, float& b) {
    asm("mov.b64 {%0,%1}, %2;" : "=f"(a), "=f"(b) : "l"(v));
}
__device__ __forceinline__ ull ffma2(ull a, ull b, ull c) {
    ull d; asm("fma.rn.f32x2 %0, %1, %2, %3;" : "=l"(d) : "l"(a), "l"(b), "l"(c));
    return d;
}

// ---------------- K0: zero stat accumulators ----------------
__global__ void k_zero() {
    int t = threadIdx.x;
    if (t < 8)  g_stats1[t] = 0.0;
    if (t < 16) g_stats2[t] = 0.0;
}

// ---------------- K1: conv1 + bias + relu + maxpool + bn1 stats ----------------
// 5 bands per image, 12 output rows per band. Input: 31 rows x 128 cols x 3 ch.
// smem: [0,1944) duplicated weights [tap(243)][oc(4)][2]; then input planar
// si[c][y][(col&1)*64 + (col>>1)]; si reused as sout[oc][12][60]; then 8 stat floats.
#define SM1_WD     1944
#define SM1_IN     (3*31*128)
#define SM1_FLOATS (SM1_WD + SM1_IN + 16)
#define SM1_BYTES  (SM1_FLOATS*4)

__global__ __launch_bounds__(192)
void k_conv1(const float* __restrict__ x, const float* __restrict__ w1,
             const float* __restrict__ b1) {
    extern __shared__ float sm[];
    float* swd = sm;                   // dup weights: [tap*8 + oc*2 + {0,1}]
    float* si  = sm + SM1_WD;
    float* ps  = sm + SM1_WD + SM1_IN; // ps[0..3]=sum per ch, ps[4..7]=sumsq
    const int bx = blockIdx.x;
    const int n = bx / 5, band = bx - n*5;
    const int tid = threadIdx.x;

    if (tid < 8) ps[tid] = 0.f;
    // duplicated weights: i = tap*4 + oc
    for (int i = tid; i < 972; i += 192) {
        int oc = i & 3, tap = i >> 2;
        int c = tap / 81, r = tap - c*81;
        float w = w1[(oc*3 + c)*81 + r];
        swd[i*2] = w; swd[i*2 + 1] = w;
    }
    // input rows [24*band, 24*band+31) : 11904 contiguous floats
    const float4* xb4 = (const float4*)(x + (size_t)n*(IMGD*IMGD*3) + (size_t)(24*band)*384);
    for (int i = tid; i < SM1_IN/4; i += 192) {
        float4 v = xb4[i];
        int j = i*4;
        #pragma unroll
        for (int e = 0; e < 4; ++e) {
            int jj = j + e;
            int y = jj / 384; int rem = jj - y*384;
            int col = rem / 3; int c = rem - col*3;
            float val = (e==0) ? v.x : (e==1) ? v.y : (e==2) ? v.z : v.w;
            si[(c*31 + y)*128 + ((col & 1) << 6) + (col >> 1)] = val;
        }
    }
    __syncthreads();

    const int warp = tid >> 5, lane = tid & 31;
    const int h = warp & 1, g = warp >> 1;     // col-half, row-group (4 rows)
    const int lx = (lane < 30) ? lane : 29;
    const int ox = h*30 + lx;
    const bool active = (lane < 30);

    ull acc[2][4];
    #pragma unroll
    for (int p = 0; p < 2; ++p) { acc[p][0]=acc[p][1]=acc[p][2]=acc[p][3]=0ull; }

    for (int c = 0; c < 3; ++c) {
        for (int ky = 0; ky < 9; ++ky) {
            const float* r0 = &si[(c*31 + 8*g + ky)*128];
            const float* wb = &swd[((c*9 + ky)*9)*8];
            #pragma unroll
            for (int kx = 0; kx < 9; ++kx) {
                const ulonglong2 q0 = *(const ulonglong2*)(wb + kx*8);      // dup oc0, oc1
                const ulonglong2 q1 = *(const ulonglong2*)(wb + kx*8 + 4);  // dup oc2, oc3
                int scol = ((kx & 1) << 6) + ox + (kx >> 1);
                float v0 = r0[scol      ];   // out row 4g
                float v1 = r0[scol + 256];   // out row 4g+1
                float v2 = r0[scol + 512];   // out row 4g+2
                float v3 = r0[scol + 768];   // out row 4g+3
                ull pA = pack2(v0, v1), pB = pack2(v2, v3);
                acc[0][0] = ffma2(pA, q0.x, acc[0][0]);
                acc[0][1] = ffma2(pA, q0.y, acc[0][1]);
                acc[0][2] = ffma2(pA, q1.x, acc[0][2]);
                acc[0][3] = ffma2(pA, q1.y, acc[0][3]);
                acc[1][0] = ffma2(pB, q0.x, acc[1][0]);
                acc[1][1] = ffma2(pB, q0.y, acc[1][1]);
                acc[1][2] = ffma2(pB, q1.x, acc[1][2]);
                acc[1][3] = ffma2(pB, q1.y, acc[1][3]);
            }
        }
    }
    float bb[4] = {b1[0], b1[1], b1[2], b1[3]};
    __syncthreads();                     // all reads of si done
    float* sout = si;                    // alias: sout[oc*720 + row*60 + col]
    if (active) {
        #pragma unroll
        for (int p = 0; p < 2; ++p) {
            #pragma unroll
            for (int oc = 0; oc < 4; ++oc) {
                float lo, hi; unpack2(acc[p][oc], lo, hi);
                int row = 4*g + 2*p;
                sout[oc*720 + row*60 + ox]       = fmaxf(lo + bb[oc], 0.f);
                sout[oc*720 + (row + 1)*60 + ox] = fmaxf(hi + bb[oc], 0.f);
            }
        }
    }
    __syncthreads();

    // pool 2x2 on 12x60 -> 6x30 per channel; stats via smem float atomics
    for (int i = tid; i < 720; i += 192) {
        int oc = i / 180, r = i - oc*180;
        int pr = r / 30, pc = r - pr*30;
        const float* b0 = &sout[oc*720 + (2*pr)*60 + 2*pc];
        float2 t0 = *(const float2*)b0;
        float2 t1 = *(const float2*)(b0 + 60);
        float m = fmaxf(fmaxf(t0.x, t0.y), fmaxf(t1.x, t1.y));
        g_pool1[((size_t)n*4 + oc)*900 + (6*band + pr)*30 + pc] = m;
        atomicAdd(&ps[oc], m);
        atomicAdd(&ps[4 + oc], m*m);
    }
    __syncthreads();
    if (tid < 8) atomicAdd(&g_stats1[tid], (double)ps[tid]);
}

// ---------------- K2: fold bn1 + conv2 + relu + maxpool + bn2 stats ----------------
__global__ __launch_bounds__(128)
void k_conv2(const float* __restrict__ w2, const float* __restrict__ b2,
             const float* __restrict__ g1, const float* __restrict__ bt1) {
    __shared__ float sp[4*30*33];
    __shared__ __align__(16) float sw[2592];
    __shared__ float sout[8*121];
    __shared__ float a1[4], sh1[4], b2e[8], sstat[16], bred[128];
    const int n = blockIdx.x, tid = threadIdx.x;

    if (tid < 4) {
        double invn = 1.0 / (800.0 * 900.0);
        float mean = (float)(g_stats1[tid] * invn);
        float var  = (float)(g_stats1[4+tid] * invn) - mean*mean;
        float a = g1[tid] * rsqrtf(var + 1e-5f);
        a1[tid] = a; sh1[tid] = bt1[tid] - mean * a;
    }
    if (tid < 16) sstat[tid] = 0.f;
    __syncthreads();

    const float* src = g_pool1 + (size_t)n*3600;
    for (int i = tid; i < 3600; i += 128) {
        int c = i / 900; int rem = i - c*900;
        int y = rem / 30; int col = rem - y*30;
        sp[(c*30 + y)*33 + ((col & 1) << 4) + (col >> 1)] = src[i];
    }
    for (int i = tid; i < 2592; i += 128) {
        int o = i & 7, rest = i >> 3;
        int c = rest / 81, tap = rest - c*81;
        sw[i] = w2[(o*4 + c)*81 + tap] * a1[c];
    }
    // parallel bias fold: tid = part*8 + oc
    {
        const int oc = tid & 7, part = tid >> 3;       // 16 parts
        float acc = 0.f;
        for (int idx = part; idx < 324; idx += 16) {
            int c = idx / 81, t = idx - c*81;
            acc += w2[(oc*4 + c)*81 + t] * sh1[c];
        }
        bred[tid] = acc;
    }
    __syncthreads();
    if (tid < 8) {
        float s = b2[tid];
        #pragma unroll
        for (int p = 0; p < 16; ++p) s += bred[p*8 + tid];
        b2e[tid] = s;
    }
    __syncthreads();

    if (tid < 121) {
        const int oy = tid / 11, ox = tid - oy*11;
        ull acc[4] = {0ull, 0ull, 0ull, 0ull};
        for (int c = 0; c < 4; ++c) {
            for (int ky = 0; ky < 9; ++ky) {
                const float* rb = &sp[(c*30 + 2*oy + ky)*33];
                const ull* wr = (const ull*)&sw[(c*81 + ky*9)*8];
                #pragma unroll
                for (int kx = 0; kx < 9; ++kx) {
                    float v = rb[((kx & 1) << 4) + ox + (kx >> 1)];
                    ull vv = pack2(v, v);
                    acc[0] = ffma2(vv, wr[kx*4    ], acc[0]);
                    acc[1] = ffma2(vv, wr[kx*4 + 1], acc[1]);
                    acc[2] = ffma2(vv, wr[kx*4 + 2], acc[2]);
                    acc[3] = ffma2(vv, wr[kx*4 + 3], acc[3]);
                }
            }
        }
        #pragma unroll
        for (int p = 0; p < 4; ++p) {
            float lo, hi; unpack2(acc[p], lo, hi);
            sout[(2*p  )*121 + tid] = fmaxf(lo + b2e[2*p  ], 0.f);
            sout[(2*p+1)*121 + tid] = fmaxf(hi + b2e[2*p+1], 0.f);
        }
    }
    __syncthreads();

    for (int i = tid; i < 200; i += 128) {
        int oc = i / 25, j = i - oc*25;
        int py = j / 5, px = j - py*5;
        const float* r0 = &sout[oc*121 + 2*py*11 + 2*px];
        float m = fmaxf(fmaxf(r0[0], r0[1]), fmaxf(r0[11], r0[12]));
        g_pool2[((size_t)n*8 + oc)*25 + j] = m;
        atomicAdd(&sstat[oc], m);
        atomicAdd(&sstat[8 + oc], m*m);
    }
    __syncthreads();
    if (tid < 16) atomicAdd(&g_stats2[tid], (double)sstat[tid]);
}

// ---------------- K3: fold bn2 + FC chain -> z, R ----------------
__global__ __launch_bounds__(256)
void k_fc(const float* __restrict__ fc1w, const float* __restrict__ fc1b,
          const float* __restrict__ fc2w, const float* __restrict__ fc2b,
          const float* __restrict__ zw, const float* __restrict__ zb,
          const float* __restrict__ Lw, const float* __restrict__ Lb,
          const float* __restrict__ g2, const float* __restrict__ bt2) {
    __shared__ __align__(16) float s_w1[3200];
    __shared__ float s_b1[16], s_w2[512], s_b2[32], s_zw[64], s_zb[2], s_Lw[96], s_Lb[3];
    __shared__ float a2[8], sh2[8], bred[256];
    const int tid = threadIdx.x;
    if (tid < 8) {
        double invn = 1.0 / 20000.0;
        float mean = (float)(g_stats2[tid] * invn);
        float var  = (float)(g_stats2[8+tid] * invn) - mean*mean;
        float a = g2[tid] * rsqrtf(var + 1e-5f);
        a2[tid] = a; sh2[tid] = bt2[tid] - mean * a;
    }
    __syncthreads();
    for (int i = tid; i < 3200; i += 256) {
        int j = i & 15, k = i >> 4;
        s_w1[i] = fc1w[j*200 + k] * a2[k / 25];
    }
    // parallel s_b1: tid = part*16 + j, 16 parts x 16 outputs
    {
        const int j = tid & 15, part = tid >> 4;
        float acc = 0.f;
        for (int k = part; k < 200; k += 16) acc += fc1w[j*200 + k] * sh2[k / 25];
        bred[tid] = acc;
    }
    for (int i = tid; i < 512; i += 256) s_w2[i] = fc2w[i];
    if (tid < 32) s_b2[tid] = fc2b[tid];
    if (tid < 64) s_zw[tid] = zw[tid];
    if (tid < 2) s_zb[tid] = zb[tid];
    if (tid < 96) s_Lw[tid] = Lw[tid];
    if (tid < 3) s_Lb[tid] = Lb[tid];
    __syncthreads();
    if (tid < 16) {
        float s = fc1b[tid];
        #pragma unroll
        for (int p = 0; p < 16; ++p) s += bred[p*16 + tid];
        s_b1[tid] = s;
    }
    __syncthreads();

    const int s = blockIdx.x*256 + tid;
    if (s >= NB) return;
    const float4* f4 = (const float4*)(g_pool2 + (size_t)s*200);
    ull hacc[8];
    #pragma unroll
    for (int j = 0; j < 8; ++j) hacc[j] = pack2(s_b1[2*j], s_b1[2*j+1]);
    #pragma unroll 2
    for (int q = 0; q < 50; ++q) {
        float4 v = f4[q];
        #pragma unroll
        for (int e = 0; e < 4; ++e) {
            float vf = (e==0) ? v.x : (e==1) ? v.y : (e==2) ? v.z : v.w;
            ull vv = pack2(vf, vf);
            const ull* wr = (const ull*)&s_w1[(q*4 + e)*16];
            #pragma unroll
            for (int j = 0; j < 8; ++j) hacc[j] = ffma2(vv, wr[j], hacc[j]);
        }
    }
    float h1[16];
    #pragma unroll
    for (int j = 0; j < 8; ++j) {
        float lo, hi; unpack2(hacc[j], lo, hi);
        h1[2*j] = fmaxf(lo, 0.f); h1[2*j+1] = fmaxf(hi, 0.f);
    }
    float h2[32];
    #pragma unroll
    for (int j = 0; j < 32; ++j) {
        float a = s_b2[j];
        #pragma unroll
        for (int k = 0; k < 16; ++k) a = fmaf(s_w2[j*16 + k], h1[k], a);
        h2[j] = fmaxf(a, 0.f);
    }
    float z0 = s_zb[0], z1 = s_zb[1], L0 = s_Lb[0], L1 = s_Lb[1], L2 = s_Lb[2];
    #pragma unroll
    for (int k = 0; k < 32; ++k) {
        z0 = fmaf(s_zw[k],      h2[k], z0);
        z1 = fmaf(s_zw[32 + k], h2[k], z1);
        L0 = fmaf(s_Lw[k],      h2[k], L0);
        L1 = fmaf(s_Lw[32 + k], h2[k], L1);
        L2 = fmaf(s_Lw[64 + k], h2[k], L2);
    }
    float* o = g_zR + (size_t)s*5;
    o[0] = z0; o[1] = z1;
    o[2] = L0*L0; o[3] = L0*L1; o[4] = L1*L1 + L2*L2;
}

// ---------------- K4: Kalman filter (1 warp, 1 thread/sequence) ----------------
__device__ __forceinline__ constexpr int SIDX(int i, int j) {
    return (i <= j) ? (i*(7 - i))/2 + j : (j*(7 - j))/2 + i;
}
#define S_(i,j)  sarr[SIDX(i,j)]
#define SP_(i,j) sp[SIDX(i,j)]

__global__ __launch_bounds__(32)
void k_kf(const float* __restrict__ A_, const float* __restrict__ B_,
          const float* __restrict__ C_, const float* __restrict__ Q_,
          float* __restrict__ out) {
    __shared__ __align__(16) float sz[NB*5];
    __shared__ float sA[16], sC[8], sBQ[16];
    const int tid = threadIdx.x;
    {
        const float4* zr4 = (const float4*)g_zR;
        float4* sz4 = (float4*)sz;
        for (int i = tid; i < NB*5/4; i += 32) sz4[i] = zr4[i];
    }
    if (tid < 16) sA[tid] = A_[tid];
    if (tid < 8)  sC[tid] = C_[tid];
    if (tid == 0) {
        float BQ[8];
        for (int i = 0; i < 4; ++i)
            for (int a = 0; a < 2; ++a)
                BQ[i*2+a] = B_[i*2]*Q_[a] + B_[i*2+1]*Q_[2+a];
        for (int i = 0; i < 4; ++i)
            for (int j = 0; j < 4; ++j)
                sBQ[i*4+j] = BQ[i*2]*B_[j*2] + BQ[i*2+1]*B_[j*2+1];
    }
    __syncthreads();
    if (tid >= 8) return;
    const int b = tid;
    float A[16], C[8], BQ[16];
    #pragma unroll
    for (int i = 0; i < 16; ++i) A[i] = sA[i];
    #pragma unroll
    for (int i = 0; i < 8;  ++i) C[i] = sC[i];
    #pragma unroll
    for (int i = 0; i < 16; ++i) BQ[i] = sBQ[i];

    const float* zr = sz + b*500;
    float h[4], sarr[10];
    h[0] = zr[0]; h[1] = zr[1]; h[2] = 0.f; h[3] = 0.f;
    sarr[0] = zr[2]; sarr[1] = zr[3]; sarr[2] = 0.f; sarr[3] = 0.f;
    sarr[4] = zr[4]; sarr[5] = 0.f;  sarr[6] = 0.f;
    sarr[7] = 1.f;   sarr[8] = 0.f;  sarr[9] = 1.f;

    float* ob = out + b*400;
    ob[0]=h[0]; ob[1]=h[1]; ob[2]=h[2]; ob[3]=h[3];

    for (int t = 1; t < 100; ++t) {
        const float* p = zr + t*5;
        float zt0 = p[0], zt1 = p[1], r00 = p[2], r01 = p[3], r11 = p[4];
        float hp[4];
        #pragma unroll
        for (int i = 0; i < 4; ++i)
            hp[i] = A[i*4]*h[0] + A[i*4+1]*h[1] + A[i*4+2]*h[2] + A[i*4+3]*h[3];
        float M[16];
        #pragma unroll
        for (int i = 0; i < 4; ++i)
            #pragma unroll
            for (int j = 0; j < 4; ++j)
                M[i*4+j] = A[i*4]*S_(0,j) + A[i*4+1]*S_(1,j)
                         + A[i*4+2]*S_(2,j) + A[i*4+3]*S_(3,j);
        float sp[10];
        #pragma unroll
        for (int i = 0; i < 4; ++i)
            #pragma unroll
            for (int j = 0; j < 4; ++j)
                if (j >= i)
                    sp[SIDX(i,j)] = M[i*4]*A[j*4] + M[i*4+1]*A[j*4+1]
                                  + M[i*4+2]*A[j*4+2] + M[i*4+3]*A[j*4+3] + BQ[i*4+j];
        float PT[8];
        #pragma unroll
        for (int i = 0; i < 4; ++i)
            #pragma unroll
            for (int a = 0; a < 2; ++a)
                PT[i*2+a] = SP_(i,0)*C[a*4] + SP_(i,1)*C[a*4+1]
                          + SP_(i,2)*C[a*4+2] + SP_(i,3)*C[a*4+3];
        float S00 = C[0]*PT[0]+C[1]*PT[2]+C[2]*PT[4]+C[3]*PT[6] + r00;
        float S01 = C[0]*PT[1]+C[1]*PT[3]+C[2]*PT[5]+C[3]*PT[7] + r01;
        float S10 = C[4]*PT[0]+C[5]*PT[2]+C[6]*PT[4]+C[7]*PT[6] + r01;
        float S11 = C[4]*PT[1]+C[5]*PT[3]+C[6]*PT[5]+C[7]*PT[7] + r11;
        float inv = 1.0f / (S00*S11 - S01*S10);
        float i00 =  S11*inv, i01 = -S01*inv, i10 = -S10*inv, i11 = S00*inv;
        float K[8];
        #pragma unroll
        for (int i = 0; i < 4; ++i) {
            K[i*2]   = PT[i*2]*i00 + PT[i*2+1]*i10;
            K[i*2+1] = PT[i*2]*i01 + PT[i*2+1]*i11;
        }
        float al0 = zt0 - (C[0]*hp[0]+C[1]*hp[1]+C[2]*hp[2]+C[3]*hp[3]);
        float al1 = zt1 - (C[4]*hp[0]+C[5]*hp[1]+C[6]*hp[2]+C[7]*hp[3]);
        #pragma unroll
        for (int i = 0; i < 4; ++i) h[i] = hp[i] + K[i*2]*al0 + K[i*2+1]*al1;
        float sn[10];
        #pragma unroll
        for (int i = 0; i < 4; ++i)
            #pragma unroll
            for (int j = 0; j < 4; ++j)
                if (j >= i)
                    sn[SIDX(i,j)] = SP_(i,j) - K[i*2]*PT[j*2] - K[i*2+1]*PT[j*2+1];
        #pragma unroll
        for (int i = 0; i < 10; ++i) sarr[i] = sn[i];
        float* op = ob + t*4;
        op[0]=h[0]; op[1]=h[1]; op[2]=h[2]; op[3]=h[3];
    }
}

// ---------------- launch ----------------
extern "C" void kernel_launch(void* const* d_in, const int* in_sizes, int n_in,
                              void* d_out, int out_size) {
    (void)in_sizes; (void)n_in; (void)out_size;
    const float* x    = (const float*)d_in[0];
    const float* w1   = (const float*)d_in[1];
    const float* b1   = (const float*)d_in[2];
    const float* bn1g = (const float*)d_in[3];
    const float* bn1b = (const float*)d_in[4];
    const float* w2   = (const float*)d_in[5];
    const float* b2   = (const float*)d_in[6];
    const float* bn2g = (const float*)d_in[7];
    const float* bn2b = (const float*)d_in[8];
    const float* fc1w = (const float*)d_in[9];
    const float* fc1b = (const float*)d_in[10];
    const float* fc2w = (const float*)d_in[11];
    const float* fc2b = (const float*)d_in[12];
    const float* f3zw = (const float*)d_in[13];
    const float* f3zb = (const float*)d_in[14];
    const float* f3Lw = (const float*)d_in[15];
    const float* f3Lb = (const float*)d_in[16];
    const float* Am   = (const float*)d_in[17];
    const float* Bm   = (const float*)d_in[18];
    const float* Cm   = (const float*)d_in[19];
    const float* Qm   = (const float*)d_in[20];

    (void)cudaFuncSetAttribute(k_conv1, cudaFuncAttributeMaxDynamicSharedMemorySize, SM1_BYTES);

    k_zero <<<1, 32>>>();
    k_conv1<<<NB*5, 192, SM1_BYTES>>>(x, w1, b1);
    k_conv2<<<NB, 128>>>(w2, b2, bn1g, bn1b);
    k_fc   <<<4, 256>>>(fc1w, fc1b, fc2w, fc2b, f3zw, f3zb, f3Lw, f3Lb, bn2g, bn2b);
    k_kf   <<<1, 32>>>(Am, Bm, Cm, Qm, (float*)d_out);
}